// round 5
// baseline (speedup 1.0000x reference)
#include <cuda_runtime.h>
#include <cuda_fp16.h>
#include <cstdint>
#include <cstddef>

#define DI __device__ __forceinline__

// ---------------- problem constants ----------------
constexpr int BATCH = 4096;
constexpr int INF   = 1024;
constexpr int OUTF  = 1024;
constexpr int KSP   = INF * 8;       // 8192 spline K
constexpr int KTOT  = KSP + INF;     // 9216 total K
constexpr int KBLK  = 64;            // fp16 per K-tile -> 128 B rows (SW128)
constexpr int NKT   = KTOT / KBLK;   // 144 K-tiles
constexpr int NKT_SP = KSP / KBLK;   // 128 spline K-tiles
constexpr int TM    = 128;
constexpr int TN    = 256;
constexpr int MT    = BATCH / TM;    // 32
constexpr int NT    = OUTF / TN;     // 4
constexpr int STAGES = 4;
constexpr int A_TILE_B = TM * KBLK * 2;       // 16384
constexpr int B_TILE_B = TN * KBLK * 2;       // 32768
constexpr int STAGE_B  = A_TILE_B + B_TILE_B; // 49152

constexpr int SOFF_FULL  = 0;    // 4 x 8B
constexpr int SOFF_EMPTY = 32;   // 4 x 8B
constexpr int SOFF_STAGE = 1024;
constexpr int SMEM_NEED  = 1024 + SOFF_STAGE + STAGES * STAGE_B; // 198656 < 227KB cap

// ---------------- scratch (device globals; no allocation) ----------------
__device__ __half g_B[(size_t)NT * NKT * TN * KBLK];  // 18.9 MB tiled+swizzled weights

// ---------------- PTX helpers ----------------
DI uint32_t s2u(const void* p) {
    uint32_t a;
    asm("{ .reg .u64 t; cvta.to.shared.u64 t, %1; cvt.u32.u64 %0, t; }" : "=r"(a) : "l"(p));
    return a;
}
DI uint32_t swz(uint32_t off) { return off ^ ((off >> 3) & 0x70); }

DI void sts128(uint32_t addr, uint4 v) {   // REAL shared-space 16B store
    asm volatile("st.shared.v4.b32 [%0], {%1,%2,%3,%4};"
                 :: "r"(addr), "r"(v.x), "r"(v.y), "r"(v.z), "r"(v.w) : "memory");
}

DI void mbar_init(uint32_t a, uint32_t cnt) {
    asm volatile("mbarrier.init.shared.b64 [%0], %1;" :: "r"(a), "r"(cnt) : "memory");
}
DI void mbar_arrive(uint32_t a) {
    asm volatile("mbarrier.arrive.release.cta.shared.b64 _, [%0];" :: "r"(a) : "memory");
}
DI void mbar_expect_tx(uint32_t a, uint32_t bytes) {
    asm volatile("mbarrier.arrive.expect_tx.shared.b64 _, [%0], %1;" :: "r"(a), "r"(bytes) : "memory");
}
DI void mbar_wait(uint32_t a, uint32_t parity) {
    asm volatile(
        "{\n\t"
        ".reg .pred P1;\n\t"
        "WAIT_LOOP_%=:\n\t"
        "mbarrier.try_wait.parity.acquire.cta.shared::cta.b64 P1, [%0], %1, 0x989680;\n\t"
        "@P1 bra.uni WAIT_DONE_%=;\n\t"
        "bra.uni WAIT_LOOP_%=;\n\t"
        "WAIT_DONE_%=:\n\t"
        "}"
        :: "r"(a), "r"(parity) : "memory");
}
DI void bulk_g2s(uint32_t dst, const void* src, uint32_t bytes, uint32_t mbar) {
    asm volatile(
        "cp.async.bulk.shared::cluster.global.mbarrier::complete_tx::bytes [%0], [%1], %2, [%3];"
        :: "r"(dst), "l"(src), "r"(bytes), "r"(mbar) : "memory");
}
DI void ldsm4(uint32_t* r, uint32_t addr) {
    asm volatile("ldmatrix.sync.aligned.m8n8.x4.shared.b16 {%0,%1,%2,%3}, [%4];"
                 : "=r"(r[0]), "=r"(r[1]), "=r"(r[2]), "=r"(r[3]) : "r"(addr));
}
DI void mma_f16(float* c, const uint32_t* a, uint32_t b0, uint32_t b1) {
    asm volatile(
        "mma.sync.aligned.m16n8k16.row.col.f32.f16.f16.f32 "
        "{%0,%1,%2,%3}, {%4,%5,%6,%7}, {%8,%9}, {%0,%1,%2,%3};"
        : "+f"(c[0]), "+f"(c[1]), "+f"(c[2]), "+f"(c[3])
        : "r"(a[0]), "r"(a[1]), "r"(a[2]), "r"(a[3]), "r"(b0), "r"(b1));
}

// ---- Cox-de-Boor bases for one scalar x -> 8 fp16 values packed as uint4 ----
DI uint4 bases8_fp16(float xv) {
    // tanh(x) = 1 - 2/(e^{2x}+1)
    float t = 1.0f - __fdividef(2.0f, __expf(2.0f * xv) + 1.0f);

    float g[12];
#pragma unroll
    for (int j = 0; j < 12; j++) g[j] = fmaf(0.4f, (float)j, -2.2f);

    constexpr float R1 = 1.0f / (0.4f + 1e-8f);
    constexpr float R2 = 1.0f / (0.8f + 1e-8f);
    constexpr float R3 = 1.0f / (1.2f + 1e-8f);
    const float RK[3] = {R1, R2, R3};

    float bas[11];
#pragma unroll
    for (int n = 0; n < 11; n++) bas[n] = (t >= g[n] && t < g[n + 1]) ? 1.0f : 0.0f;

#pragma unroll
    for (int k = 1; k <= 3; k++) {
        float rk = RK[k - 1];
#pragma unroll
        for (int j = 0; j < 11 - k; j++) {
            float left  = (t - g[j]) * rk;
            float right = (g[j + k + 1] - t) * rk;
            bas[j] = left * bas[j] + right * bas[j + 1];
        }
    }
    __half hv[8];
#pragma unroll
    for (int n = 0; n < 8; n++) hv[n] = __float2half_rn(bas[n]);
    return *reinterpret_cast<uint4*>(hv);
}

// ---------------- prologue B: re-tile + swizzle weights to fp16 ----------------
__global__ void __launch_bounds__(256) prolog_b(const float* __restrict__ spw,
                                                const float* __restrict__ baw) {
    int idx = blockIdx.x * 256 + threadIdx.x;
    int o  = idx / (KTOT / 8);
    int kq = idx % (KTOT / 8);
    int k  = kq * 8;
    float4 v0, v1;
    if (k < KSP) {
        const float4* p = reinterpret_cast<const float4*>(spw + (size_t)o * KSP + k);
        v0 = p[0]; v1 = p[1];
    } else {
        const float4* p = reinterpret_cast<const float4*>(baw + (size_t)o * INF + (k - KSP));
        v0 = p[0]; v1 = p[1];
    }
    __half hv[8];
    hv[0] = __float2half_rn(v0.x); hv[1] = __float2half_rn(v0.y);
    hv[2] = __float2half_rn(v0.z); hv[3] = __float2half_rn(v0.w);
    hv[4] = __float2half_rn(v1.x); hv[5] = __float2half_rn(v1.y);
    hv[6] = __float2half_rn(v1.z); hv[7] = __float2half_rn(v1.w);

    int nt = o >> 8, row = o & 255;
    int kt = k >> 6;
    size_t tile = ((size_t)(nt * NKT + kt)) * B_TILE_B;
    uint32_t off = (uint32_t)(row * 128 + (k & 63) * 2);
    *reinterpret_cast<uint4*>((char*)g_B + tile + swz(off)) = *reinterpret_cast<uint4*>(hv);
}

// ---------------- fused GEMM: in-kernel A production + mma.sync mainloop ----------------
struct GemmCtx {
    uint32_t sb;
    const float* x;
    int mt;
};

// Produce A tile for k-tile j directly into smem stage (all 256 threads), then
// kick B bulk copy and arrive on the full barrier.
DI void produce_stage(const GemmCtx& c, int j, int tid, const char* bgl) {
    int s = j & (STAGES - 1);
    uint32_t sa = c.sb + SOFF_STAGE + s * STAGE_B;
    int row = tid & 127;
    const float* xrow = c.x + (size_t)(c.mt * 128 + row) * INF;

    if (j < NKT_SP) {
        // spline tile: i in [j*8, j*8+8); this thread does 4 consecutive i
        int i0 = j * 8 + (tid >> 7) * 4;
        float4 xv = *reinterpret_cast<const float4*>(xrow + i0);
        uint32_t base = (uint32_t)(row * 128 + (i0 & 7) * 16);
        sts128(sa + swz(base),      bases8_fp16(xv.x));
        sts128(sa + swz(base + 16), bases8_fp16(xv.y));
        sts128(sa + swz(base + 32), bases8_fp16(xv.z));
        sts128(sa + swz(base + 48), bases8_fp16(xv.w));
    } else {
        // silu tile: i in [(j-128)*64, +64); this thread does 4 octets of 8 i
        int ib = (j - NKT_SP) * 64;
        int g0 = tid >> 7;  // 0 or 1
#pragma unroll
        for (int q = 0; q < 4; q++) {
            int oc = g0 + q * 2;
            const float4* p = reinterpret_cast<const float4*>(xrow + ib + oc * 8);
            float4 a = p[0], b = p[1];
            __half hv[8];
            hv[0] = __float2half_rn(__fdividef(a.x, 1.0f + __expf(-a.x)));
            hv[1] = __float2half_rn(__fdividef(a.y, 1.0f + __expf(-a.y)));
            hv[2] = __float2half_rn(__fdividef(a.z, 1.0f + __expf(-a.z)));
            hv[3] = __float2half_rn(__fdividef(a.w, 1.0f + __expf(-a.w)));
            hv[4] = __float2half_rn(__fdividef(b.x, 1.0f + __expf(-b.x)));
            hv[5] = __float2half_rn(__fdividef(b.y, 1.0f + __expf(-b.y)));
            hv[6] = __float2half_rn(__fdividef(b.z, 1.0f + __expf(-b.z)));
            hv[7] = __float2half_rn(__fdividef(b.w, 1.0f + __expf(-b.w)));
            sts128(sa + swz((uint32_t)(row * 128 + oc * 16)),
                   *reinterpret_cast<uint4*>(hv));
        }
    }
    uint32_t full = c.sb + SOFF_FULL + 8 * s;
    if (tid == 0) {
        mbar_expect_tx(full, B_TILE_B);  // counts as this thread's arrive + tx
        bulk_g2s(sa + A_TILE_B, bgl + (size_t)j * B_TILE_B, B_TILE_B, full);
    } else {
        mbar_arrive(full);
    }
}

__global__ void __launch_bounds__(256, 1) kan_gemm(float* __restrict__ out,
                                                   const float* __restrict__ x) {
    extern __shared__ __align__(16) char smem_raw[];
    uint32_t sb = (s2u(smem_raw) + 1023u) & ~1023u;
    int tid = threadIdx.x, wid = tid >> 5, lane = tid & 31;
    int warp_m = wid >> 2, warp_n = wid & 3;   // 2 x 4 warp grid, 64x64 per warp

    if (tid == 0) {
        for (int s = 0; s < STAGES; s++) {
            mbar_init(sb + SOFF_FULL  + 8 * s, 256);
            mbar_init(sb + SOFF_EMPTY + 8 * s, 256);
        }
    }
    __syncthreads();

    int mt = blockIdx.x, nt = blockIdx.y;
    const char* bgl = (const char*)g_B + (size_t)nt * NKT * B_TILE_B;
    GemmCtx ctx{sb, x, mt};

    // ---- per-thread ldmatrix addressing (swizzle-folded) ----
    int g = lane >> 3, r = lane & 7;
    int rA = warp_m * 64 + (g & 1) * 8 + r;
    uint32_t acol0 = (uint32_t)((g >> 1) * 16);
    uint32_t amask = (uint32_t)((rA & 7) << 4);
    int rB = warp_n * 64 + ((g >> 1) & 1) * 8 + r;
    uint32_t bcol0 = (uint32_t)((g & 1) * 16);
    uint32_t bmask = (uint32_t)((rB & 7) << 4);
    uint32_t acol[4], bcol[4];
#pragma unroll
    for (int ks = 0; ks < 4; ks++) {
        acol[ks] = (acol0 + ks * 32) ^ amask;
        bcol[ks] = (bcol0 + ks * 32) ^ bmask;
    }
    uint32_t aRowOff = (uint32_t)(rA * 128);
    uint32_t bRowOff = (uint32_t)(A_TILE_B + rB * 128);

    float acc[4][8][4];
#pragma unroll
    for (int mi = 0; mi < 4; mi++)
#pragma unroll
        for (int nj = 0; nj < 8; nj++)
#pragma unroll
            for (int q = 0; q < 4; q++) acc[mi][nj][q] = 0.0f;

    // ---- prologue: produce first STAGES-1 stages ----
#pragma unroll 1
    for (int p = 0; p < STAGES - 1; p++) produce_stage(ctx, p, tid, bgl);

    int fphase = 0, ephase = 0;
#pragma unroll 1
    for (int kt = 0; kt < NKT; kt++) {
        int s = kt & (STAGES - 1);
        mbar_wait(sb + SOFF_FULL + 8 * s, fphase);
        if (s == STAGES - 1) fphase ^= 1;

        uint32_t sbase = sb + SOFF_STAGE + s * STAGE_B;
        uint32_t baseA = sbase + aRowOff;
        uint32_t baseB = sbase + bRowOff;

        // --- first half of MMAs (fills the tensor pipe) ---
#pragma unroll
        for (int ks = 0; ks < 2; ks++) {
            uint32_t af[4][4], bf[4][4];
#pragma unroll
            for (int mi = 0; mi < 4; mi++) ldsm4(af[mi], baseA + mi * 2048 + acol[ks]);
#pragma unroll
            for (int np = 0; np < 4; np++) ldsm4(bf[np], baseB + np * 2048 + bcol[ks]);
#pragma unroll
            for (int mi = 0; mi < 4; mi++)
#pragma unroll
                for (int nj = 0; nj < 8; nj++)
                    mma_f16(acc[mi][nj], af[mi],
                            bf[nj >> 1][(nj & 1) * 2], bf[nj >> 1][(nj & 1) * 2 + 1]);
        }

        // --- produce stage kt+STAGES-1 while the issued MMAs drain ---
        {
            int j = kt + STAGES - 1;
            if (j < NKT) {
                int sp = j & (STAGES - 1);
                if (j >= STAGES) {
                    mbar_wait(sb + SOFF_EMPTY + 8 * sp, ephase);
                    if (sp == STAGES - 1) ephase ^= 1;
                }
                produce_stage(ctx, j, tid, bgl);
            }
        }

        // --- second half of MMAs ---
#pragma unroll
        for (int ks = 2; ks < 4; ks++) {
            uint32_t af[4][4], bf[4][4];
#pragma unroll
            for (int mi = 0; mi < 4; mi++) ldsm4(af[mi], baseA + mi * 2048 + acol[ks]);
#pragma unroll
            for (int np = 0; np < 4; np++) ldsm4(bf[np], baseB + np * 2048 + bcol[ks]);
#pragma unroll
            for (int mi = 0; mi < 4; mi++)
#pragma unroll
                for (int nj = 0; nj < 8; nj++)
                    mma_f16(acc[mi][nj], af[mi],
                            bf[nj >> 1][(nj & 1) * 2], bf[nj >> 1][(nj & 1) * 2 + 1]);
        }
        mbar_arrive(sb + SOFF_EMPTY + 8 * s);
    }

    // ---- epilogue: FP32 accumulators -> global ----
    int row0 = mt * 128 + warp_m * 64 + (lane >> 2);
    int col0 = nt * 256 + warp_n * 64 + (lane & 3) * 2;
#pragma unroll
    for (int mi = 0; mi < 4; mi++) {
#pragma unroll
        for (int nj = 0; nj < 8; nj++) {
            float* p0 = out + (size_t)(row0 + mi * 16) * OUTF + col0 + nj * 8;
            float* p1 = out + (size_t)(row0 + mi * 16 + 8) * OUTF + col0 + nj * 8;
            *reinterpret_cast<float2*>(p0) = make_float2(acc[mi][nj][0], acc[mi][nj][1]);
            *reinterpret_cast<float2*>(p1) = make_float2(acc[mi][nj][2], acc[mi][nj][3]);
        }
    }
}

// ---------------- host launch ----------------
extern "C" void kernel_launch(void* const* d_in, const int* in_sizes, int n_in,
                              void* d_out, int out_size) {
    (void)in_sizes; (void)n_in; (void)out_size;
    const float* x   = (const float*)d_in[0];
    const float* spw = (const float*)d_in[1];
    const float* baw = (const float*)d_in[2];
    float* out = (float*)d_out;

    prolog_b<<<(OUTF * (KTOT / 8)) / 256, 256>>>(spw, baw);

    static int smem_set = 0;
    if (!smem_set) {
        cudaFuncSetAttribute(kan_gemm, cudaFuncAttributeMaxDynamicSharedMemorySize, SMEM_NEED);
        smem_set = 1;
    }
    kan_gemm<<<dim3(MT, NT), 256, SMEM_NEED>>>(out, x);
}